// round 5
// baseline (speedup 1.0000x reference)
#include <cuda_runtime.h>

#define WID 1024
#define HEI 1024
#define CH  3
#define KR  10            // taps from -10..10
#define BS  256
#define TILE (BS + 2*KR)  // 276

__global__ __launch_bounds__(BS) void gauss_h_kernel(
    const float* __restrict__ x,
    const float* __restrict__ sigma,
    float* __restrict__ out)
{
    __shared__ float sm[CH][TILE];

    const int y   = blockIdx.y;
    const int x0  = blockIdx.x * BS;
    const int tid = threadIdx.x;

    // Load row tile per channel with clamp-to-edge
    const float* row = x + y * WID;
    #pragma unroll
    for (int c = 0; c < CH; ++c) {
        const float* rc = row + c * (HEI * WID);
        #pragma unroll
        for (int j = tid; j < TILE; j += BS) {
            int gx = x0 + j - KR;
            gx = min(max(gx, 0), WID - 1);
            sm[c][j] = rc[gx];
        }
    }
    __syncthreads();

    const int xg = x0 + tid;
    const float sig = sigma[y * WID + xg];
    const float s2  = sig * sig;
    // t = exp(-1/(2*sigma^2)); w_i = t^(i^2) via incremental recurrence
    const float t   = __expf(__fdividef(-0.5f, s2));
    const float hs  = ceilf(2.0f * sig);   // half_step
    const float t2  = t * t;

    const int li = tid + KR;
    float n0 = sm[0][li];
    float n1 = sm[1][li];
    float n2 = sm[2][li];
    float norm = 1.0f;     // w_0 = 1

    float w = 1.0f;        // running t^(i^2)
    float u = t;           // running t^(2i-1)

    #pragma unroll
    for (int i = 1; i <= KR; ++i) {
        w *= u;            // w = t^(i*i)
        u *= t2;           // u = t^(2i+1)
        const float wi = ((float)i <= hs) ? w : 0.0f;
        norm += 2.0f * wi;
        n0 += wi * (sm[0][li - i] + sm[0][li + i]);
        n1 += wi * (sm[1][li - i] + sm[1][li + i]);
        n2 += wi * (sm[2][li - i] + sm[2][li + i]);
    }

    const float inv = __fdividef(1.0f, norm);
    const int o = y * WID + xg;
    out[o]                 = n0 * inv;
    out[o +     HEI * WID] = n1 * inv;
    out[o + 2 * HEI * WID] = n2 * inv;
}

extern "C" void kernel_launch(void* const* d_in, const int* in_sizes, int n_in,
                              void* d_out, int out_size)
{
    const float* x     = (const float*)d_in[0];
    const float* sigma = (const float*)d_in[1];
    float* out         = (float*)d_out;

    dim3 grid(WID / BS, HEI);
    gauss_h_kernel<<<grid, BS>>>(x, sigma, out);
}

// round 14
// speedup vs baseline: 1.0532x; 1.0532x over previous
#include <cuda_runtime.h>

#define WID 1024
#define HEI 1024
#define CH  3
#define KR  10
#define BS  128
#define PXT 4
#define SPAN (BS*PXT)        // 512 pixels per block
#define PAD  12              // left pad (multiple of 4, >= KR)
#define TILE4 136            // float4s per channel: covers floats [x0-12, x0+531]

__device__ __forceinline__ float f4get(const float4 (&v)[7], int m) {
    const float4 f = v[m >> 2];
    switch (m & 3) {
        case 0:  return f.x;
        case 1:  return f.y;
        case 2:  return f.z;
        default: return f.w;
    }
}

__global__ __launch_bounds__(BS) void gauss_h4_kernel(
    const float* __restrict__ x,
    const float* __restrict__ sigma,
    float* __restrict__ out)
{
    __shared__ float4 sm[CH][TILE4];

    const int y   = blockIdx.y;
    const int x0  = blockIdx.x * SPAN;
    const int tid = threadIdx.x;
    const int g0  = x0 - PAD;

    // ---- cooperative tile load, float4 with scalar clamp fallback at edges ----
    #pragma unroll
    for (int c = 0; c < CH; ++c) {
        const float* rc = x + (c * HEI + y) * WID;
        for (int j = tid; j < TILE4; j += BS) {
            const int g = g0 + 4 * j;
            float4 v;
            if (g >= 0 && g + 3 < WID) {
                v = *reinterpret_cast<const float4*>(rc + g);
            } else {
                v.x = rc[min(max(g + 0, 0), WID - 1)];
                v.y = rc[min(max(g + 1, 0), WID - 1)];
                v.z = rc[min(max(g + 2, 0), WID - 1)];
                v.w = rc[min(max(g + 3, 0), WID - 1)];
            }
            sm[c][j] = v;
        }
    }
    __syncthreads();

    // ---- per-pixel weights (computed once, masked, pre-scaled by 1/norm) ----
    const int px = x0 + 4 * tid;
    const float4 sg4 = *reinterpret_cast<const float4*>(sigma + y * WID + px);
    const float sgs[4] = { sg4.x, sg4.y, sg4.z, sg4.w };

    float wk[4][KR];   // wk[k][i-1] = masked weight_i * inv_norm
    float w0[4];       // inv_norm (center weight is 1)

    #pragma unroll
    for (int k = 0; k < 4; ++k) {
        const float sig = sgs[k];
        const float t   = __expf(__fdividef(-0.5f, sig * sig));
        const float hs  = ceilf(2.0f * sig);
        const float t2  = t * t;
        float w = 1.0f, u = t, norm = 1.0f;
        #pragma unroll
        for (int i = 1; i <= KR; ++i) {
            w *= u;              // w = t^(i*i)
            u *= t2;             // u = t^(2i+1)
            const float wi = ((float)i <= hs) ? w : 0.0f;
            wk[k][i - 1] = wi;
            norm += 2.0f * wi;
        }
        const float inv = __fdividef(1.0f, norm);
        w0[k] = inv;
        #pragma unroll
        for (int i = 0; i < KR; ++i) wk[k][i] *= inv;
    }

    // ---- channel loop: register window of 28 floats, 7x LDS.128 each ----
    float* op = out + y * WID + px;
    #pragma unroll
    for (int c = 0; c < CH; ++c) {
        float4 wv[7];
        #pragma unroll
        for (int j = 0; j < 7; ++j) wv[j] = sm[c][tid + j];

        float accf[4];
        #pragma unroll
        for (int k = 0; k < 4; ++k) {
            // pixel px+k maps to smem float index (4*tid + k + PAD); window-local m0 = k + 12
            float acc = f4get(wv, k + 12) * w0[k];
            #pragma unroll
            for (int i = 1; i <= KR; ++i)
                acc += wk[k][i - 1] * (f4get(wv, k + 12 - i) + f4get(wv, k + 12 + i));
            accf[k] = acc;
        }
        float4 r;
        r.x = accf[0]; r.y = accf[1]; r.z = accf[2]; r.w = accf[3];
        *reinterpret_cast<float4*>(op + c * HEI * WID) = r;
    }
}

extern "C" void kernel_launch(void* const* d_in, const int* in_sizes, int n_in,
                              void* d_out, int out_size)
{
    const float* x     = (const float*)d_in[0];
    const float* sigma = (const float*)d_in[1];
    float* out         = (float*)d_out;

    dim3 grid(WID / SPAN, HEI);
    gauss_h4_kernel<<<grid, BS>>>(x, sigma, out);
}

// round 15
// speedup vs baseline: 1.8205x; 1.7286x over previous
#include <cuda_runtime.h>

#define WID 1024
#define HEI 1024
#define CH  3
#define KR  10
#define BS  128
#define PXT 4
#define SPAN (BS*PXT)        // 512 pixels per block
#define PAD  12              // left pad (multiple of 4, >= KR)
#define TILE4 136            // float4s per channel: floats [x0-12, x0+531]

__device__ __forceinline__ float f4get(const float4 (&v)[7], int m) {
    const float4 f = v[m >> 2];
    switch (m & 3) {
        case 0:  return f.x;
        case 1:  return f.y;
        case 2:  return f.z;
        default: return f.w;
    }
}

__global__ __launch_bounds__(BS, 7) void gauss_h4_kernel(
    const float* __restrict__ x,
    const float* __restrict__ sigma,
    float* __restrict__ out)
{
    __shared__ float4 sm[CH][TILE4];

    const int y   = blockIdx.y;
    const int x0  = blockIdx.x * SPAN;
    const int tid = threadIdx.x;
    const int g0  = x0 - PAD;

    // ---- tile load (issued first so LDG latency overlaps the weight pre-pass) ----
    #pragma unroll
    for (int c = 0; c < CH; ++c) {
        const float* rc = x + (c * HEI + y) * WID;
        for (int j = tid; j < TILE4; j += BS) {
            const int g = g0 + 4 * j;
            float4 v;
            if (g >= 0 && g + 3 < WID) {
                v = *reinterpret_cast<const float4*>(rc + g);
            } else {
                v.x = rc[min(max(g + 0, 0), WID - 1)];
                v.y = rc[min(max(g + 1, 0), WID - 1)];
                v.z = rc[min(max(g + 2, 0), WID - 1)];
                v.w = rc[min(max(g + 3, 0), WID - 1)];
            }
            sm[c][j] = v;
        }
    }

    // ---- weight pre-pass (channel-independent): t, t2, hs, inv_norm per pixel ----
    const int px = x0 + 4 * tid;
    const float4 sg4 = *reinterpret_cast<const float4*>(sigma + y * WID + px);
    const float sgs[4] = { sg4.x, sg4.y, sg4.z, sg4.w };

    float tk[4], t2k[4], hsk[4], invk[4];
    #pragma unroll
    for (int k = 0; k < 4; ++k) {
        const float sig = sgs[k];
        const float t   = __expf(__fdividef(-0.5f, sig * sig));
        const float hs  = ceilf(2.0f * sig);
        const float t2  = t * t;
        float w = 1.0f, u = t, norm = 1.0f;
        #pragma unroll
        for (int i = 1; i <= KR; ++i) {
            w *= u;
            u *= t2;
            norm += ((float)i <= hs) ? 2.0f * w : 0.0f;
        }
        tk[k]   = t;
        t2k[k]  = t2;
        hsk[k]  = hs;
        invk[k] = __fdividef(1.0f, norm);
    }

    __syncthreads();

    // ---- channel loop: 28-float register window, weights recomputed per channel ----
    float* op = out + y * WID + px;
    #pragma unroll
    for (int c = 0; c < CH; ++c) {
        float4 wv[7];
        #pragma unroll
        for (int j = 0; j < 7; ++j) wv[j] = sm[c][tid + j];

        float accf[4];
        #pragma unroll
        for (int k = 0; k < 4; ++k) {
            // pixel px+k -> window-local center index k+12
            float w = 1.0f, u = tk[k];
            float acc = f4get(wv, k + 12);          // center weight = 1
            const float t2 = t2k[k];
            const float hs = hsk[k];
            #pragma unroll
            for (int i = 1; i <= KR; ++i) {
                w *= u;                              // w = t^(i*i)
                u *= t2;                             // u = t^(2i+1)
                const float wi = ((float)i <= hs) ? w : 0.0f;
                acc += wi * (f4get(wv, k + 12 - i) + f4get(wv, k + 12 + i));
            }
            accf[k] = acc * invk[k];
        }
        float4 r;
        r.x = accf[0]; r.y = accf[1]; r.z = accf[2]; r.w = accf[3];
        *reinterpret_cast<float4*>(op + c * HEI * WID) = r;
    }
}

extern "C" void kernel_launch(void* const* d_in, const int* in_sizes, int n_in,
                              void* d_out, int out_size)
{
    const float* x     = (const float*)d_in[0];
    const float* sigma = (const float*)d_in[1];
    float* out         = (float*)d_out;

    dim3 grid(WID / SPAN, HEI);
    gauss_h4_kernel<<<grid, BS>>>(x, sigma, out);
}